// round 2
// baseline (speedup 1.0000x reference)
#include <cuda_runtime.h>
#include <math.h>

#define T_STEPS 300
#define DIN 39
#define H1D 35
#define H2D 30
#define G1 140
#define G2 120
#define K1 74
#define K2 65
#define BT 64
#define BTP 68
#define NT 256
#define BATCH 4096
#define NBLK (BATCH/BT)

// ---- shared memory layout for the LSTM kernel (float offsets) ----
#define OFF_W1 0
#define OFF_W2 (OFF_W1 + K1*G1)        // 10360
#define OFF_B1 (OFF_W2 + K2*G2)        // 18160
#define OFF_B2 (OFF_B1 + G1)           // 18300
#define OFF_X  (OFF_B2 + G2)           // 18420
#define OFF_H1 (OFF_X + DIN*BTP)       // 21072
#define OFF_C1 (OFF_H1 + H1D*BTP)      // 23452
#define OFF_H2 (OFF_C1 + H1D*BTP)      // 25832
#define OFF_C2 (OFF_H2 + H2D*BTP)      // 27872
#define OFF_Z  (OFF_C2 + H2D*BTP)      // 29912
#define SM_FLOATS (OFF_Z + G1*BTP)     // 39432 floats = 157728 B

// scratch for LSTM hidden states: [B][T][60], fw in [0,30), bw in [30,60)
__device__ float g_hbuf[(size_t)BATCH * T_STEPS * 60];

__device__ __forceinline__ float sigf(float x) {
    return __fdividef(1.0f, 1.0f + __expf(-x));
}
__device__ __forceinline__ float tanhfast(float x) {
    // tanh(x) = 2*sigmoid(2x) - 1
    return 2.0f * sigf(2.0f * x) - 1.0f;
}

// 4-gate x 8-batch register-tile GEMM fragment.
// w: column pointer into weight matrix (row stride GS), a: activation row (row stride BTP)
template<int KN, int GS>
__device__ __forceinline__ void gemm48(float (&acc)[4][8],
                                       const float* __restrict__ w,
                                       const float* __restrict__ a)
{
    #pragma unroll 5
    for (int k = 0; k < KN; ++k) {
        float4 wv = *(const float4*)w;
        float4 a0 = *(const float4*)a;
        float4 a1 = *(const float4*)(a + 4);
        w += GS; a += BTP;
        float wr[4] = {wv.x, wv.y, wv.z, wv.w};
        float ar[8] = {a0.x, a0.y, a0.z, a0.w, a1.x, a1.y, a1.z, a1.w};
        #pragma unroll
        for (int gi = 0; gi < 4; ++gi)
            #pragma unroll
            for (int bi = 0; bi < 8; ++bi)
                acc[gi][bi] = fmaf(wr[gi], ar[bi], acc[gi][bi]);
    }
}

// 1-gate x 8-batch fragment (leftover gates 128..139 of layer 1)
template<int KN, int GS>
__device__ __forceinline__ void gemm18(float (&acc)[8],
                                       const float* __restrict__ w,
                                       const float* __restrict__ a)
{
    #pragma unroll 5
    for (int k = 0; k < KN; ++k) {
        float wv = *w;
        float4 a0 = *(const float4*)a;
        float4 a1 = *(const float4*)(a + 4);
        w += GS; a += BTP;
        float ar[8] = {a0.x, a0.y, a0.z, a0.w, a1.x, a1.y, a1.z, a1.w};
        #pragma unroll
        for (int bi = 0; bi < 8; ++bi)
            acc[bi] = fmaf(wv, ar[bi], acc[bi]);
    }
}

extern __shared__ float smem[];

__global__ void __launch_bounds__(NT)
lstm_kernel(const float* __restrict__ x,
            const float* __restrict__ fw_W1, const float* __restrict__ fw_b1,
            const float* __restrict__ fw_W2, const float* __restrict__ fw_b2,
            const float* __restrict__ bw_W1, const float* __restrict__ bw_b1,
            const float* __restrict__ bw_W2, const float* __restrict__ bw_b2)
{
    const int dir = blockIdx.y;
    const int b0  = blockIdx.x * BT;
    const int tid = threadIdx.x;

    float* W1s = smem + OFF_W1;
    float* W2s = smem + OFF_W2;
    float* b1s = smem + OFF_B1;
    float* b2s = smem + OFF_B2;
    float* xT  = smem + OFF_X;
    float* h1T = smem + OFF_H1;
    float* c1T = smem + OFF_C1;
    float* h2T = smem + OFF_H2;
    float* c2T = smem + OFF_C2;
    float* zs  = smem + OFF_Z;

    const float* W1g = dir ? bw_W1 : fw_W1;
    const float* b1g = dir ? bw_b1 : fw_b1;
    const float* W2g = dir ? bw_W2 : fw_W2;
    const float* b2g = dir ? bw_b2 : fw_b2;

    for (int i = tid; i < K1*G1; i += NT) W1s[i] = W1g[i];
    for (int i = tid; i < K2*G2; i += NT) W2s[i] = W2g[i];
    for (int i = tid; i < G1; i += NT) b1s[i] = b1g[i];
    for (int i = tid; i < G2; i += NT) b2s[i] = b2g[i];
    for (int i = tid; i < H1D*BTP; i += NT) { h1T[i] = 0.f; c1T[i] = 0.f; }
    for (int i = tid; i < H2D*BTP; i += NT) { h2T[i] = 0.f; c2T[i] = 0.f; }

    const int rowA = tid >> 3;          // 0..31
    const int bcol = (tid & 7) * 8;     // batch offset within tile
    const int gA   = rowA * 4;          // 4 gates per thread

    for (int t = 0; t < T_STEPS; ++t) {
        __syncthreads();
        const int tx = dir ? (T_STEPS - 1 - t) : t;

        // stage x_t transposed [d][b]
        for (int i = tid; i < DIN*BT; i += NT) {
            int b = i / DIN, d = i - b * DIN;
            xT[d * BTP + b] = x[((size_t)(b0 + b) * T_STEPS + tx) * DIN + d];
        }
        __syncthreads();

        // ---- layer-1 GEMM: z = [x_t, h1] @ W1 + b1 (gates 0..127) ----
        {
            float acc[4][8];
            #pragma unroll
            for (int gi = 0; gi < 4; ++gi) {
                float bb = b1s[gA + gi];
                #pragma unroll
                for (int bi = 0; bi < 8; ++bi) acc[gi][bi] = bb;
            }
            gemm48<DIN, G1>(acc, W1s + gA,            xT  + bcol);
            gemm48<H1D, G1>(acc, W1s + DIN*G1 + gA,   h1T + bcol);
            #pragma unroll
            for (int gi = 0; gi < 4; ++gi) {
                *(float4*)(zs + (gA+gi)*BTP + bcol)     =
                    make_float4(acc[gi][0], acc[gi][1], acc[gi][2], acc[gi][3]);
                *(float4*)(zs + (gA+gi)*BTP + bcol + 4) =
                    make_float4(acc[gi][4], acc[gi][5], acc[gi][6], acc[gi][7]);
            }
        }
        // leftover gates 128..139
        if (tid < 96) {
            const int gB = 128 + (tid >> 3);
            float acc[8];
            float bb = b1s[gB];
            #pragma unroll
            for (int bi = 0; bi < 8; ++bi) acc[bi] = bb;
            gemm18<DIN, G1>(acc, W1s + gB,          xT  + bcol);
            gemm18<H1D, G1>(acc, W1s + DIN*G1 + gB, h1T + bcol);
            *(float4*)(zs + gB*BTP + bcol)     = make_float4(acc[0], acc[1], acc[2], acc[3]);
            *(float4*)(zs + gB*BTP + bcol + 4) = make_float4(acc[4], acc[5], acc[6], acc[7]);
        }
        __syncthreads();

        // ---- layer-1 cell update ----
        for (int i = tid; i < H1D*BT; i += NT) {
            int j = i >> 6, b = i & 63;
            int o = j * BTP + b;
            float iv = zs[o];
            float jv = zs[H1D*BTP + o];
            float fv = zs[2*H1D*BTP + o];
            float ov = zs[3*H1D*BTP + o];
            float c  = sigf(fv + 1.0f) * c1T[o] + sigf(iv) * tanhfast(jv);
            c1T[o] = c;
            h1T[o] = sigf(ov) * tanhfast(c);
        }
        __syncthreads();

        // ---- layer-2 GEMM: z = [h1, h2] @ W2 + b2 (120 gates) ----
        if (rowA < 30) {
            float acc[4][8];
            #pragma unroll
            for (int gi = 0; gi < 4; ++gi) {
                float bb = b2s[gA + gi];
                #pragma unroll
                for (int bi = 0; bi < 8; ++bi) acc[gi][bi] = bb;
            }
            gemm48<H1D, G2>(acc, W2s + gA,            h1T + bcol);
            gemm48<H2D, G2>(acc, W2s + H1D*G2 + gA,   h2T + bcol);
            #pragma unroll
            for (int gi = 0; gi < 4; ++gi) {
                *(float4*)(zs + (gA+gi)*BTP + bcol)     =
                    make_float4(acc[gi][0], acc[gi][1], acc[gi][2], acc[gi][3]);
                *(float4*)(zs + (gA+gi)*BTP + bcol + 4) =
                    make_float4(acc[gi][4], acc[gi][5], acc[gi][6], acc[gi][7]);
            }
        }
        __syncthreads();

        // ---- layer-2 cell update + write h to global scratch ----
        for (int i = tid; i < H2D*BT; i += NT) {
            int b = i / H2D, j = i - b * H2D;
            int o = j * BTP + b;
            float iv = zs[o];
            float jv = zs[H2D*BTP + o];
            float fv = zs[2*H2D*BTP + o];
            float ov = zs[3*H2D*BTP + o];
            float c  = sigf(fv + 1.0f) * c2T[o] + sigf(iv) * tanhfast(jv);
            c2T[o] = c;
            float h = sigf(ov) * tanhfast(c);
            h2T[o] = h;
            g_hbuf[((size_t)(b0 + b) * T_STEPS + tx) * 60 + dir * H2D + j] = h;
        }
    }
}

// =============================== FC head ===================================
#define FCT 128
#define FOFF_W1 0                       // 60*52 = 3120 (padded cols 50,51 = 0)
#define FOFF_W2 (FOFF_W1 + 60*52)       // 3120, size 2000
#define FOFF_W3 (FOFF_W2 + 50*40)       // 5120, size 80
#define FOFF_B1 (FOFF_W3 + 80)          // 5200, size 52
#define FOFF_B2 (FOFF_B1 + 52)          // 5252, size 40
#define FOFF_B3 (FOFF_B2 + 40)          // 5292, size 4 (padded)
#define FOFF_IN (FOFF_B3 + 4)           // 5296, size FCT*61
#define FSM_FLOATS (FOFF_IN + FCT*61)   // 13104 floats = 52416 B

__global__ void __launch_bounds__(FCT)
fc_kernel(const float* __restrict__ Wf1, const float* __restrict__ bf1,
          const float* __restrict__ Wf2, const float* __restrict__ bf2,
          const float* __restrict__ Wf3, const float* __restrict__ bf3,
          float* __restrict__ out)
{
    extern __shared__ float fsm[];
    float* W1s = fsm + FOFF_W1;
    float* W2s = fsm + FOFF_W2;
    float* W3s = fsm + FOFF_W3;
    float* B1s = fsm + FOFF_B1;
    float* B2s = fsm + FOFF_B2;
    float* B3s = fsm + FOFF_B3;
    float* INs = fsm + FOFF_IN;

    const int tid = threadIdx.x;

    for (int i = tid; i < 60*52; i += FCT) {
        int k = i / 52, j = i - k * 52;
        W1s[i] = (j < 50) ? Wf1[k*50 + j] : 0.f;
    }
    for (int i = tid; i < 50*40; i += FCT) W2s[i] = Wf2[i];
    for (int i = tid; i < 80;    i += FCT) W3s[i] = Wf3[i];
    for (int i = tid; i < 52;    i += FCT) B1s[i] = (i < 50) ? bf1[i] : 0.f;
    for (int i = tid; i < 40;    i += FCT) B2s[i] = bf2[i];
    for (int i = tid; i < 2;     i += FCT) B3s[i] = bf3[i];

    const size_t pbase = (size_t)blockIdx.x * FCT;
    // coalesced stage of 128 x 60 inputs
    for (int i = tid; i < FCT*60; i += FCT) {
        int pl = i / 60, f = i - pl * 60;
        INs[pl*61 + f] = g_hbuf[pbase * 60 + i];
    }
    __syncthreads();

    // fc1: 60 -> 50 (padded to 52), k-outer so inputs are read once
    float a1[52];
    #pragma unroll
    for (int j = 0; j < 52; ++j) a1[j] = B1s[j];
    #pragma unroll
    for (int k = 0; k < 60; ++k) {
        float v = INs[tid*61 + k];
        #pragma unroll
        for (int j = 0; j < 52; j += 4) {
            float4 w = *(const float4*)(W1s + k*52 + j);
            a1[j+0] = fmaf(v, w.x, a1[j+0]);
            a1[j+1] = fmaf(v, w.y, a1[j+1]);
            a1[j+2] = fmaf(v, w.z, a1[j+2]);
            a1[j+3] = fmaf(v, w.w, a1[j+3]);
        }
    }
    #pragma unroll
    for (int j = 0; j < 50; ++j) a1[j] = fmaxf(a1[j], 0.f);

    // fc2: 50 -> 40
    float a2[40];
    #pragma unroll
    for (int j = 0; j < 40; ++j) a2[j] = B2s[j];
    #pragma unroll
    for (int k = 0; k < 50; ++k) {
        float v = a1[k];
        #pragma unroll
        for (int j = 0; j < 40; j += 4) {
            float4 w = *(const float4*)(W2s + k*40 + j);
            a2[j+0] = fmaf(v, w.x, a2[j+0]);
            a2[j+1] = fmaf(v, w.y, a2[j+1]);
            a2[j+2] = fmaf(v, w.z, a2[j+2]);
            a2[j+3] = fmaf(v, w.w, a2[j+3]);
        }
    }
    #pragma unroll
    for (int j = 0; j < 40; ++j) a2[j] = fmaxf(a2[j], 0.f);

    // out: 40 -> 2
    float o0 = B3s[0], o1 = B3s[1];
    #pragma unroll
    for (int k = 0; k < 40; ++k) {
        o0 = fmaf(a2[k], W3s[2*k + 0], o0);
        o1 = fmaf(a2[k], W3s[2*k + 1], o1);
    }
    const size_t p = pbase + tid;
    out[p*2 + 0] = o0;
    out[p*2 + 1] = o1;
}

// ============================================================================
extern "C" void kernel_launch(void* const* d_in, const int* in_sizes, int n_in,
                              void* d_out, int out_size)
{
    const float* x     = (const float*)d_in[0];
    const float* fw_W1 = (const float*)d_in[1];
    const float* fw_b1 = (const float*)d_in[2];
    const float* fw_W2 = (const float*)d_in[3];
    const float* fw_b2 = (const float*)d_in[4];
    const float* bw_W1 = (const float*)d_in[5];
    const float* bw_b1 = (const float*)d_in[6];
    const float* bw_W2 = (const float*)d_in[7];
    const float* bw_b2 = (const float*)d_in[8];
    const float* Wf1   = (const float*)d_in[9];
    const float* bf1   = (const float*)d_in[10];
    const float* Wf2   = (const float*)d_in[11];
    const float* bf2   = (const float*)d_in[12];
    const float* Wf3   = (const float*)d_in[13];
    const float* bf3   = (const float*)d_in[14];

    cudaFuncSetAttribute(lstm_kernel, cudaFuncAttributeMaxDynamicSharedMemorySize,
                         SM_FLOATS * (int)sizeof(float));
    cudaFuncSetAttribute(fc_kernel, cudaFuncAttributeMaxDynamicSharedMemorySize,
                         FSM_FLOATS * (int)sizeof(float));

    lstm_kernel<<<dim3(NBLK, 2), NT, SM_FLOATS * sizeof(float)>>>(
        x, fw_W1, fw_b1, fw_W2, fw_b2, bw_W1, bw_b1, bw_W2, bw_b2);

    fc_kernel<<<(BATCH * T_STEPS) / FCT, FCT, FSM_FLOATS * sizeof(float)>>>(
        Wf1, bf1, Wf2, bf2, Wf3, bf3, (float*)d_out);
}

// round 3
// speedup vs baseline: 1.0962x; 1.0962x over previous
#include <cuda_runtime.h>
#include <math.h>

#define T_STEPS 300
#define DIN 39
#define H1D 35
#define H2D 30
#define G1 140
#define G2 120
#define K1 74
#define K2 65
#define BT 64
#define BTP 68
#define NT 256
#define BATCH 4096
#define NBLK (BATCH/BT)

typedef unsigned long long ull;

// ---- shared memory layout (float offsets) ----
#define OFF_W1D 0                          // 74*280 = 20720 (duplicated, unit-major)
#define OFF_W2D (OFF_W1D + K1*2*G1)        // 20720, size 65*240 = 15600
#define OFF_B1  (OFF_W2D + K2*2*G2)        // 36320, 140
#define OFF_B2  (OFF_B1 + G1)              // 36460, 120
#define OFF_X   (OFF_B2 + G2)              // 36580, 2*39*68 = 5304
#define OFF_H1  (OFF_X + 2*DIN*BTP)        // 41884, 2*35*68 = 4760
#define OFF_H2  (OFF_H1 + 2*H1D*BTP)       // 46644, 2*30*68 = 4080
#define SM_FLOATS (OFF_H2 + 2*H2D*BTP)     // 50724 floats = 202896 B

#define X_BUF  (DIN*BTP)
#define H1_BUF (H1D*BTP)
#define H2_BUF (H2D*BTP)

// scratch for LSTM hidden states: [B][T][60], fw in [0,30), bw in [30,60)
__device__ float g_hbuf[(size_t)BATCH * T_STEPS * 60];

__device__ __forceinline__ ull fma2(ull a, ull b, ull c) {
    ull d;
    asm("fma.rn.f32x2 %0, %1, %2, %3;" : "=l"(d) : "l"(a), "l"(b), "l"(c));
    return d;
}
__device__ __forceinline__ ull pack2(float lo, float hi) {
    ull d;
    asm("mov.b64 %0, {%1, %2};" : "=l"(d) : "f"(lo), "f"(hi));
    return d;
}
__device__ __forceinline__ void unpack2(ull v, float& lo, float& hi) {
    asm("mov.b64 {%0, %1}, %2;" : "=f"(lo), "=f"(hi) : "l"(v));
}

__device__ __forceinline__ float sigf(float x) {
    return __fdividef(1.0f, 1.0f + __expf(-x));
}
__device__ __forceinline__ float tanhfast(float x) {
    return 2.0f * sigf(2.0f * x) - 1.0f;
}

// cell update on a packed pair of batch lanes; gate order i, j, f, o
__device__ __forceinline__ void cell2(ull zi, ull zj, ull zf, ull zo,
                                      ull& c, float& h0, float& h1)
{
    float i0,i1,j0,j1,f0,f1,o0,o1,c0,c1;
    unpack2(zi,i0,i1); unpack2(zj,j0,j1);
    unpack2(zf,f0,f1); unpack2(zo,o0,o1);
    unpack2(c,c0,c1);
    c0 = sigf(f0 + 1.0f) * c0 + sigf(i0) * tanhfast(j0);
    c1 = sigf(f1 + 1.0f) * c1 + sigf(i1) * tanhfast(j1);
    h0 = sigf(o0) * tanhfast(c0);
    h1 = sigf(o1) * tanhfast(c1);
    c = pack2(c0, c1);
}

// 4-gate x 4-packed-batch tile. wd: duplicated-weight row (ull, WS ull per k row).
// a: activation row (float, BTP per k row). All 16B aligned.
template<int KN, int WS>
__device__ __forceinline__ void gemm_f2(ull (&acc)[4][4],
                                        const ull* __restrict__ wd,
                                        const float* __restrict__ a)
{
    #pragma unroll 5
    for (int k = 0; k < KN; ++k) {
        ulonglong2 w01 = *(const ulonglong2*)(wd);
        ulonglong2 w23 = *(const ulonglong2*)(wd + 2);
        ulonglong2 a01 = *(const ulonglong2*)(a);
        ulonglong2 a23 = *(const ulonglong2*)(a + 4);
        wd += WS; a += BTP;
        ull wr[4] = {w01.x, w01.y, w23.x, w23.y};
        ull ar[4] = {a01.x, a01.y, a23.x, a23.y};
        #pragma unroll
        for (int g = 0; g < 4; ++g)
            #pragma unroll
            for (int p = 0; p < 4; ++p)
                acc[g][p] = fma2(wr[g], ar[p], acc[g][p]);
    }
}

// 4-gate x 1-packed-batch tile (leftover units)
template<int KN, int WS>
__device__ __forceinline__ void gemm_f2_1(ull (&acc)[4],
                                          const ull* __restrict__ wd,
                                          const float* __restrict__ a)
{
    #pragma unroll 5
    for (int k = 0; k < KN; ++k) {
        ulonglong2 w01 = *(const ulonglong2*)(wd);
        ulonglong2 w23 = *(const ulonglong2*)(wd + 2);
        ull av = *(const ull*)(a);
        wd += WS; a += BTP;
        acc[0] = fma2(w01.x, av, acc[0]);
        acc[1] = fma2(w01.y, av, acc[1]);
        acc[2] = fma2(w23.x, av, acc[2]);
        acc[3] = fma2(w23.y, av, acc[3]);
    }
}

extern __shared__ float smem[];

__global__ void __launch_bounds__(NT)
lstm_kernel(const float* __restrict__ x,
            const float* __restrict__ fw_W1, const float* __restrict__ fw_b1,
            const float* __restrict__ fw_W2, const float* __restrict__ fw_b2,
            const float* __restrict__ bw_W1, const float* __restrict__ bw_b1,
            const float* __restrict__ bw_W2, const float* __restrict__ bw_b2)
{
    const int dir = blockIdx.y;
    const int b0  = blockIdx.x * BT;
    const int tid = threadIdx.x;

    float* W1d = smem + OFF_W1D;
    float* W2d = smem + OFF_W2D;
    float* b1p = smem + OFF_B1;
    float* b2p = smem + OFF_B2;
    float* xT  = smem + OFF_X;
    float* h1T = smem + OFF_H1;
    float* h2T = smem + OFF_H2;

    const float* W1g = dir ? bw_W1 : fw_W1;
    const float* b1g = dir ? bw_b1 : fw_b1;
    const float* W2g = dir ? bw_W2 : fw_W2;
    const float* b2g = dir ? bw_b2 : fw_b2;

    // permute (unit-major gate order) + duplicate weights for f32x2
    for (int i = tid; i < K1*G1; i += NT) {
        int k = i / G1, col = i - k * G1;
        int u = col >> 2, g = col & 3;
        float w = W1g[k*G1 + g*H1D + u];
        W1d[k*2*G1 + 2*col]     = w;
        W1d[k*2*G1 + 2*col + 1] = w;
    }
    for (int i = tid; i < K2*G2; i += NT) {
        int k = i / G2, col = i - k * G2;
        int u = col >> 2, g = col & 3;
        float w = W2g[k*G2 + g*H2D + u];
        W2d[k*2*G2 + 2*col]     = w;
        W2d[k*2*G2 + 2*col + 1] = w;
    }
    for (int i = tid; i < G1; i += NT) { int u = i >> 2, g = i & 3; b1p[i] = b1g[g*H1D + u]; }
    for (int i = tid; i < G2; i += NT) { int u = i >> 2, g = i & 3; b2p[i] = b2g[g*H2D + u]; }
    for (int i = tid; i < H1_BUF; i += NT) h1T[i] = 0.f;
    for (int i = tid; i < H2_BUF; i += NT) h2T[i] = 0.f;

    // stage x for t=0 into buffer 0
    {
        const int tx0 = dir ? (T_STEPS - 1) : 0;
        for (int i = tid; i < DIN*BT; i += NT) {
            int b = i / DIN, d = i - b * DIN;
            xT[d * BTP + b] = x[((size_t)(b0 + b) * T_STEPS + tx0) * DIN + d];
        }
    }
    __syncthreads();

    const int unit = tid >> 3;          // 0..31
    const int bcol = (tid & 7) * 8;     // batch offset in tile

    ull c1r[4] = {0,0,0,0};
    ull c1L    = 0;
    ull c2r[4] = {0,0,0,0};

    int cur = 0;

    for (int t = 0; t < T_STEPS; ++t) {
        const int nxt = cur ^ 1;
        const float* xc  = xT  + cur * X_BUF;
        const float* h1c = h1T + cur * H1_BUF;
        float*       h1n = h1T + nxt * H1_BUF;
        const float* h2c = h2T + cur * H2_BUF;
        float*       h2n = h2T + nxt * H2_BUF;

        // ================= Phase A: layer 1 =================
        {
            ull acc[4][4];
            #pragma unroll
            for (int g = 0; g < 4; ++g) {
                float bb = b1p[unit*4 + g];
                ull bp = pack2(bb, bb);
                #pragma unroll
                for (int p = 0; p < 4; ++p) acc[g][p] = bp;
            }
            const ull* wd = (const ull*)W1d + unit*4;
            gemm_f2<DIN, G1>(acc, wd,            xc  + bcol);
            gemm_f2<H1D, G1>(acc, wd + DIN*G1,   h1c + bcol);

            float h[8];
            #pragma unroll
            for (int p = 0; p < 4; ++p)
                cell2(acc[0][p], acc[1][p], acc[2][p], acc[3][p],
                      c1r[p], h[2*p], h[2*p+1]);
            float* dst = h1n + unit*BTP + bcol;
            *(float4*)(dst)     = make_float4(h[0], h[1], h[2], h[3]);
            *(float4*)(dst + 4) = make_float4(h[4], h[5], h[6], h[7]);
        }

        if (tid < 96) {
            // leftover units 32..34 (warp w handles unit 32+w, 2 batch lanes/thread)
            const int u    = 32 + (tid >> 5);
            const int bofs = (tid & 31) * 2;
            ull acc[4];
            #pragma unroll
            for (int g = 0; g < 4; ++g) {
                float bb = b1p[u*4 + g];
                acc[g] = pack2(bb, bb);
            }
            const ull* wd = (const ull*)W1d + u*4;
            gemm_f2_1<DIN, G1>(acc, wd,          xc  + bofs);
            gemm_f2_1<H1D, G1>(acc, wd + DIN*G1, h1c + bofs);
            float h0, h1v;
            cell2(acc[0], acc[1], acc[2], acc[3], c1L, h0, h1v);
            *(ull*)(h1n + u*BTP + bofs) = pack2(h0, h1v);
        } else if (t + 1 < T_STEPS) {
            // warps 3..7 stage x_{t+1} into the other buffer
            const int txn = dir ? (T_STEPS - 2 - t) : (t + 1);
            float* xn = xT + nxt * X_BUF;
            for (int i = tid - 96; i < DIN*BT; i += 160) {
                int b = i / DIN, d = i - b * DIN;
                xn[d * BTP + b] = x[((size_t)(b0 + b) * T_STEPS + txn) * DIN + d];
            }
        }
        __syncthreads();

        // ================= Phase B: layer 2 =================
        if (unit < 30) {
            ull acc[4][4];
            #pragma unroll
            for (int g = 0; g < 4; ++g) {
                float bb = b2p[unit*4 + g];
                ull bp = pack2(bb, bb);
                #pragma unroll
                for (int p = 0; p < 4; ++p) acc[g][p] = bp;
            }
            const ull* wd = (const ull*)W2d + unit*4;
            gemm_f2<H1D, G2>(acc, wd,            h1n + bcol);
            gemm_f2<H2D, G2>(acc, wd + H1D*G2,   h2c + bcol);

            float h[8];
            #pragma unroll
            for (int p = 0; p < 4; ++p)
                cell2(acc[0][p], acc[1][p], acc[2][p], acc[3][p],
                      c2r[p], h[2*p], h[2*p+1]);
            float* dst = h2n + unit*BTP + bcol;
            *(float4*)(dst)     = make_float4(h[0], h[1], h[2], h[3]);
            *(float4*)(dst + 4) = make_float4(h[4], h[5], h[6], h[7]);

            const int tx = dir ? (T_STEPS - 1 - t) : t;
            #pragma unroll
            for (int l = 0; l < 8; ++l) {
                g_hbuf[((size_t)(b0 + bcol + l) * T_STEPS + tx) * 60 + dir * H2D + unit] = h[l];
            }
        }
        __syncthreads();
        cur = nxt;
    }
}

// =============================== FC head ===================================
#define FCT 128
#define FOFF_W1 0                       // 60*52 (padded cols 50,51 = 0)
#define FOFF_W2 (FOFF_W1 + 60*52)       // 3120, size 2000
#define FOFF_W3 (FOFF_W2 + 50*40)       // 5120, size 80
#define FOFF_B1 (FOFF_W3 + 80)          // 5200, size 52
#define FOFF_B2 (FOFF_B1 + 52)          // 5252, size 40
#define FOFF_B3 (FOFF_B2 + 40)          // 5292, size 4
#define FOFF_IN (FOFF_B3 + 4)           // 5296, size FCT*61
#define FSM_FLOATS (FOFF_IN + FCT*61)

__global__ void __launch_bounds__(FCT)
fc_kernel(const float* __restrict__ Wf1, const float* __restrict__ bf1,
          const float* __restrict__ Wf2, const float* __restrict__ bf2,
          const float* __restrict__ Wf3, const float* __restrict__ bf3,
          float* __restrict__ out)
{
    extern __shared__ float fsm[];
    float* W1s = fsm + FOFF_W1;
    float* W2s = fsm + FOFF_W2;
    float* W3s = fsm + FOFF_W3;
    float* B1s = fsm + FOFF_B1;
    float* B2s = fsm + FOFF_B2;
    float* B3s = fsm + FOFF_B3;
    float* INs = fsm + FOFF_IN;

    const int tid = threadIdx.x;

    for (int i = tid; i < 60*52; i += FCT) {
        int k = i / 52, j = i - k * 52;
        W1s[i] = (j < 50) ? Wf1[k*50 + j] : 0.f;
    }
    for (int i = tid; i < 50*40; i += FCT) W2s[i] = Wf2[i];
    for (int i = tid; i < 80;    i += FCT) W3s[i] = Wf3[i];
    for (int i = tid; i < 52;    i += FCT) B1s[i] = (i < 50) ? bf1[i] : 0.f;
    for (int i = tid; i < 40;    i += FCT) B2s[i] = bf2[i];
    for (int i = tid; i < 2;     i += FCT) B3s[i] = bf3[i];

    const size_t pbase = (size_t)blockIdx.x * FCT;
    for (int i = tid; i < FCT*60; i += FCT) {
        int pl = i / 60, f = i - pl * 60;
        INs[pl*61 + f] = g_hbuf[pbase * 60 + i];
    }
    __syncthreads();

    // fc1: 60 -> 50 (padded 52), packed f32x2 accumulators
    ull acc1[26];
    #pragma unroll
    for (int j = 0; j < 26; ++j) acc1[j] = pack2(B1s[2*j], B1s[2*j+1]);
    #pragma unroll 4
    for (int k = 0; k < 60; ++k) {
        float v = INs[tid*61 + k];
        ull vv = pack2(v, v);
        #pragma unroll
        for (int j = 0; j < 13; ++j) {
            ulonglong2 w = *(const ulonglong2*)(W1s + k*52 + j*4);
            acc1[2*j]   = fma2(vv, w.x, acc1[2*j]);
            acc1[2*j+1] = fma2(vv, w.y, acc1[2*j+1]);
        }
    }
    float a1[52];
    #pragma unroll
    for (int j = 0; j < 26; ++j) {
        float lo, hi; unpack2(acc1[j], lo, hi);
        a1[2*j]   = fmaxf(lo, 0.f);
        a1[2*j+1] = fmaxf(hi, 0.f);
    }

    // fc2: 50 -> 40
    ull acc2[20];
    #pragma unroll
    for (int j = 0; j < 20; ++j) acc2[j] = pack2(B2s[2*j], B2s[2*j+1]);
    #pragma unroll 5
    for (int k = 0; k < 50; ++k) {
        ull vv = pack2(a1[k], a1[k]);
        #pragma unroll
        for (int j = 0; j < 10; ++j) {
            ulonglong2 w = *(const ulonglong2*)(W2s + k*40 + j*4);
            acc2[2*j]   = fma2(vv, w.x, acc2[2*j]);
            acc2[2*j+1] = fma2(vv, w.y, acc2[2*j+1]);
        }
    }
    float a2[40];
    #pragma unroll
    for (int j = 0; j < 20; ++j) {
        float lo, hi; unpack2(acc2[j], lo, hi);
        a2[2*j]   = fmaxf(lo, 0.f);
        a2[2*j+1] = fmaxf(hi, 0.f);
    }

    // out: 40 -> 2
    float o0 = B3s[0], o1 = B3s[1];
    #pragma unroll
    for (int k = 0; k < 40; ++k) {
        o0 = fmaf(a2[k], W3s[2*k + 0], o0);
        o1 = fmaf(a2[k], W3s[2*k + 1], o1);
    }
    const size_t p = pbase + tid;
    out[p*2 + 0] = o0;
    out[p*2 + 1] = o1;
}

// ============================================================================
extern "C" void kernel_launch(void* const* d_in, const int* in_sizes, int n_in,
                              void* d_out, int out_size)
{
    const float* x     = (const float*)d_in[0];
    const float* fw_W1 = (const float*)d_in[1];
    const float* fw_b1 = (const float*)d_in[2];
    const float* fw_W2 = (const float*)d_in[3];
    const float* fw_b2 = (const float*)d_in[4];
    const float* bw_W1 = (const float*)d_in[5];
    const float* bw_b1 = (const float*)d_in[6];
    const float* bw_W2 = (const float*)d_in[7];
    const float* bw_b2 = (const float*)d_in[8];
    const float* Wf1   = (const float*)d_in[9];
    const float* bf1   = (const float*)d_in[10];
    const float* Wf2   = (const float*)d_in[11];
    const float* bf2   = (const float*)d_in[12];
    const float* Wf3   = (const float*)d_in[13];
    const float* bf3   = (const float*)d_in[14];

    cudaFuncSetAttribute(lstm_kernel, cudaFuncAttributeMaxDynamicSharedMemorySize,
                         SM_FLOATS * (int)sizeof(float));
    cudaFuncSetAttribute(fc_kernel, cudaFuncAttributeMaxDynamicSharedMemorySize,
                         FSM_FLOATS * (int)sizeof(float));

    lstm_kernel<<<dim3(NBLK, 2), NT, SM_FLOATS * sizeof(float)>>>(
        x, fw_W1, fw_b1, fw_W2, fw_b2, bw_W1, bw_b1, bw_W2, bw_b2);

    fc_kernel<<<(BATCH * T_STEPS) / FCT, FCT, FSM_FLOATS * sizeof(float)>>>(
        Wf1, bf1, Wf2, bf2, Wf3, bf3, (float*)d_out);
}

// round 4
// speedup vs baseline: 1.2166x; 1.1098x over previous
#include <cuda_runtime.h>
#include <math.h>

#define T_STEPS 300
#define DIN 39
#define H1D 35
#define H2D 30
#define G1 140
#define G2 120
#define K1 74
#define K2 65
#define BT 64
#define BTP 68
#define NT 512
#define BATCH 4096
#define NBLK (BATCH/BT)

typedef unsigned long long ull;

// ---- shared memory layout (float offsets) ----
#define OFF_W1D 0                          // 74*280 = 20720 (duplicated, unit-major)
#define OFF_W2D (OFF_W1D + K1*2*G1)        // 20720, size 65*240 = 15600
#define OFF_B1  (OFF_W2D + K2*2*G2)        // 36320, 140
#define OFF_B2  (OFF_B1 + G1)              // 36460, 120
#define OFF_X   (OFF_B2 + G2)              // 36580, 2*39*68
#define OFF_H1  (OFF_X + 2*DIN*BTP)        // 41884, 2*35*68
#define OFF_H2  (OFF_H1 + 2*H1D*BTP)       // 46644, 2*30*68
#define SM_FLOATS (OFF_H2 + 2*H2D*BTP)     // 50724 floats = 202896 B

#define X_BUF  (DIN*BTP)
#define H1_BUF (H1D*BTP)
#define H2_BUF (H2D*BTP)

// scratch for LSTM hidden states: [T][60][B], fw units in [0,30), bw in [30,60)
__device__ float g_hbuf[(size_t)BATCH * T_STEPS * 60];

__device__ __forceinline__ ull fma2(ull a, ull b, ull c) {
    ull d;
    asm("fma.rn.f32x2 %0, %1, %2, %3;" : "=l"(d) : "l"(a), "l"(b), "l"(c));
    return d;
}
__device__ __forceinline__ ull pack2(float lo, float hi) {
    ull d;
    asm("mov.b64 %0, {%1, %2};" : "=l"(d) : "f"(lo), "f"(hi));
    return d;
}
__device__ __forceinline__ void unpack2(ull v, float& lo, float& hi) {
    asm("mov.b64 {%0, %1}, %2;" : "=f"(lo), "=f"(hi) : "l"(v));
}

__device__ __forceinline__ float sigf(float x) {
    return __fdividef(1.0f, 1.0f + __expf(-x));
}
__device__ __forceinline__ float tanhfast(float x) {
    return 2.0f * sigf(2.0f * x) - 1.0f;
}

// cell update on a packed pair of batch lanes; gate order i, j, f, o
__device__ __forceinline__ void cell2(ull zi, ull zj, ull zf, ull zo,
                                      ull& c, float& h0, float& h1)
{
    float i0,i1,j0,j1,f0,f1,o0,o1,c0,c1;
    unpack2(zi,i0,i1); unpack2(zj,j0,j1);
    unpack2(zf,f0,f1); unpack2(zo,o0,o1);
    unpack2(c,c0,c1);
    c0 = sigf(f0 + 1.0f) * c0 + sigf(i0) * tanhfast(j0);
    c1 = sigf(f1 + 1.0f) * c1 + sigf(i1) * tanhfast(j1);
    h0 = sigf(o0) * tanhfast(c0);
    h1 = sigf(o1) * tanhfast(c1);
    c = pack2(c0, c1);
}

// 4-gate x 2-packed-batch tile (4 batch lanes per thread).
// wd: duplicated weights (ull view, WS ull per k row); a: activation row.
template<int KN, int WS>
__device__ __forceinline__ void gemm2(ull (&acc)[4][2],
                                      const ull* __restrict__ wd,
                                      const float* __restrict__ a)
{
    #pragma unroll 5
    for (int k = 0; k < KN; ++k) {
        ulonglong2 w01 = *(const ulonglong2*)(wd);
        ulonglong2 w23 = *(const ulonglong2*)(wd + 2);
        ulonglong2 av  = *(const ulonglong2*)(a);
        wd += WS; a += BTP;
        acc[0][0] = fma2(w01.x, av.x, acc[0][0]);
        acc[0][1] = fma2(w01.x, av.y, acc[0][1]);
        acc[1][0] = fma2(w01.y, av.x, acc[1][0]);
        acc[1][1] = fma2(w01.y, av.y, acc[1][1]);
        acc[2][0] = fma2(w23.x, av.x, acc[2][0]);
        acc[2][1] = fma2(w23.x, av.y, acc[2][1]);
        acc[3][0] = fma2(w23.y, av.x, acc[3][0]);
        acc[3][1] = fma2(w23.y, av.y, acc[3][1]);
    }
}

extern __shared__ float smem[];

__global__ void __launch_bounds__(NT)
lstm_kernel(const float* __restrict__ x,
            const float* __restrict__ fw_W1, const float* __restrict__ fw_b1,
            const float* __restrict__ fw_W2, const float* __restrict__ fw_b2,
            const float* __restrict__ bw_W1, const float* __restrict__ bw_b1,
            const float* __restrict__ bw_W2, const float* __restrict__ bw_b2)
{
    const int dir = blockIdx.y;
    const int b0  = blockIdx.x * BT;
    const int tid = threadIdx.x;

    float* W1d = smem + OFF_W1D;
    float* W2d = smem + OFF_W2D;
    float* b1p = smem + OFF_B1;
    float* b2p = smem + OFF_B2;
    float* xT  = smem + OFF_X;
    float* h1T = smem + OFF_H1;
    float* h2T = smem + OFF_H2;

    const float* W1g = dir ? bw_W1 : fw_W1;
    const float* b1g = dir ? bw_b1 : fw_b1;
    const float* W2g = dir ? bw_W2 : fw_W2;
    const float* b2g = dir ? bw_b2 : fw_b2;

    // permute (unit-major gate order i,j,f,o) + duplicate weights for f32x2
    for (int i = tid; i < K1*G1; i += NT) {
        int k = i / G1, col = i - k * G1;
        int u = col >> 2, g = col & 3;
        float w = W1g[k*G1 + g*H1D + u];
        W1d[k*2*G1 + 2*col]     = w;
        W1d[k*2*G1 + 2*col + 1] = w;
    }
    for (int i = tid; i < K2*G2; i += NT) {
        int k = i / G2, col = i - k * G2;
        int u = col >> 2, g = col & 3;
        float w = W2g[k*G2 + g*H2D + u];
        W2d[k*2*G2 + 2*col]     = w;
        W2d[k*2*G2 + 2*col + 1] = w;
    }
    for (int i = tid; i < G1; i += NT) { int u = i >> 2, g = i & 3; b1p[i] = b1g[g*H1D + u]; }
    for (int i = tid; i < G2; i += NT) { int u = i >> 2, g = i & 3; b2p[i] = b2g[g*H2D + u]; }
    for (int i = tid; i < H1_BUF; i += NT) h1T[i] = 0.f;
    for (int i = tid; i < H2_BUF; i += NT) h2T[i] = 0.f;

    // stage x for t=0 into buffer 0
    {
        const int tx0 = dir ? (T_STEPS - 1) : 0;
        for (int i = tid; i < DIN*BT; i += NT) {
            int b = i / DIN, d = i - b * DIN;
            xT[d * BTP + b] = x[((size_t)(b0 + b) * T_STEPS + tx0) * DIN + d];
        }
    }
    __syncthreads();

    const int unit = tid >> 4;          // 0..31
    const int bcol = (tid & 15) * 4;    // 4 batch lanes per thread

    ull c1r[2] = {0,0};
    ull c1L[2] = {0,0};   // leftover units (threads 0..47)
    ull c2r[2] = {0,0};

    int cur = 0;

    for (int t = 0; t < T_STEPS; ++t) {
        const int nxt = cur ^ 1;
        const float* xc  = xT  + cur * X_BUF;
        const float* h1c = h1T + cur * H1_BUF;
        float*       h1n = h1T + nxt * H1_BUF;
        const float* h2c = h2T + cur * H2_BUF;
        float*       h2n = h2T + nxt * H2_BUF;

        // ================= Phase A: layer 1 (units 0..31) =================
        {
            ull acc[4][2];
            #pragma unroll
            for (int g = 0; g < 4; ++g) {
                float bb = b1p[unit*4 + g];
                ull bp = pack2(bb, bb);
                acc[g][0] = bp; acc[g][1] = bp;
            }
            const ull* wd = (const ull*)W1d + unit*4;
            gemm2<DIN, G1>(acc, wd,            xc  + bcol);
            gemm2<H1D, G1>(acc, wd + DIN*G1,   h1c + bcol);

            float h[4];
            cell2(acc[0][0], acc[1][0], acc[2][0], acc[3][0], c1r[0], h[0], h[1]);
            cell2(acc[0][1], acc[1][1], acc[2][1], acc[3][1], c1r[1], h[2], h[3]);
            *(float4*)(h1n + unit*BTP + bcol) = make_float4(h[0], h[1], h[2], h[3]);
        }

        if (tid < 48) {
            // leftover units 32..34
            const int u = 32 + (tid >> 4);
            ull acc[4][2];
            #pragma unroll
            for (int g = 0; g < 4; ++g) {
                float bb = b1p[u*4 + g];
                ull bp = pack2(bb, bb);
                acc[g][0] = bp; acc[g][1] = bp;
            }
            const ull* wd = (const ull*)W1d + u*4;
            gemm2<DIN, G1>(acc, wd,            xc  + bcol);
            gemm2<H1D, G1>(acc, wd + DIN*G1,   h1c + bcol);

            float h[4];
            cell2(acc[0][0], acc[1][0], acc[2][0], acc[3][0], c1L[0], h[0], h[1]);
            cell2(acc[0][1], acc[1][1], acc[2][1], acc[3][1], c1L[1], h[2], h[3]);
            *(float4*)(h1n + u*BTP + bcol) = make_float4(h[0], h[1], h[2], h[3]);
        } else if (tid >= 96 && t + 1 < T_STEPS) {
            // warps 3..15 stage x_{t+1} into the other buffer
            const int txn = dir ? (T_STEPS - 2 - t) : (t + 1);
            float* xn = xT + nxt * X_BUF;
            for (int i = tid - 96; i < DIN*BT; i += NT - 96) {
                int b = i / DIN, d = i - b * DIN;
                xn[d * BTP + b] = x[((size_t)(b0 + b) * T_STEPS + txn) * DIN + d];
            }
        }
        __syncthreads();

        // ================= Phase B: layer 2 (units 0..29) =================
        if (unit < 30) {
            ull acc[4][2];
            #pragma unroll
            for (int g = 0; g < 4; ++g) {
                float bb = b2p[unit*4 + g];
                ull bp = pack2(bb, bb);
                acc[g][0] = bp; acc[g][1] = bp;
            }
            const ull* wd = (const ull*)W2d + unit*4;
            gemm2<H1D, G2>(acc, wd,            h1n + bcol);
            gemm2<H2D, G2>(acc, wd + H1D*G2,   h2c + bcol);

            float h[4];
            cell2(acc[0][0], acc[1][0], acc[2][0], acc[3][0], c2r[0], h[0], h[1]);
            cell2(acc[0][1], acc[1][1], acc[2][1], acc[3][1], c2r[1], h[2], h[3]);
            *(float4*)(h2n + unit*BTP + bcol) = make_float4(h[0], h[1], h[2], h[3]);

            const int tx = dir ? (T_STEPS - 1 - t) : t;
            // coalesced: [t][feat][batch]
            *(float4*)(&g_hbuf[((size_t)(tx*60 + dir*H2D + unit))*BATCH + b0 + bcol]) =
                make_float4(h[0], h[1], h[2], h[3]);
        }
        __syncthreads();
        cur = nxt;
    }
}

// =============================== FC head ===================================
#define FCT 128
#define FOFF_W1 0                       // 60*52 (padded cols 50,51 = 0)
#define FOFF_W2 (FOFF_W1 + 60*52)       // 3120, size 2000
#define FOFF_W3 (FOFF_W2 + 50*40)       // 5120, size 80
#define FOFF_B1 (FOFF_W3 + 80)          // 5200, size 52
#define FOFF_B2 (FOFF_B1 + 52)          // 5252, size 40
#define FOFF_B3 (FOFF_B2 + 40)          // 5292, size 4
#define FOFF_IN (FOFF_B3 + 4)           // 5296, size FCT*61
#define FSM_FLOATS (FOFF_IN + FCT*61)

__global__ void __launch_bounds__(FCT)
fc_kernel(const float* __restrict__ Wf1, const float* __restrict__ bf1,
          const float* __restrict__ Wf2, const float* __restrict__ bf2,
          const float* __restrict__ Wf3, const float* __restrict__ bf3,
          float* __restrict__ out)
{
    extern __shared__ float fsm[];
    float* W1s = fsm + FOFF_W1;
    float* W2s = fsm + FOFF_W2;
    float* W3s = fsm + FOFF_W3;
    float* B1s = fsm + FOFF_B1;
    float* B2s = fsm + FOFF_B2;
    float* B3s = fsm + FOFF_B3;
    float* INs = fsm + FOFF_IN;

    const int tid = threadIdx.x;

    for (int i = tid; i < 60*52; i += FCT) {
        int k = i / 52, j = i - k * 52;
        W1s[i] = (j < 50) ? Wf1[k*50 + j] : 0.f;
    }
    for (int i = tid; i < 50*40; i += FCT) W2s[i] = Wf2[i];
    for (int i = tid; i < 80;    i += FCT) W3s[i] = Wf3[i];
    for (int i = tid; i < 52;    i += FCT) B1s[i] = (i < 50) ? bf1[i] : 0.f;
    for (int i = tid; i < 40;    i += FCT) B2s[i] = bf2[i];
    for (int i = tid; i < 2;     i += FCT) B3s[i] = bf3[i];

    // block = (batch tile, timestep): hbuf reads coalesced in new layout
    const int bi = blockIdx.x & 31;          // 32 tiles of 128 batch
    const int t  = blockIdx.x >> 5;          // 0..299
    const int b0 = bi * FCT;

    for (int i = tid; i < FCT*60; i += FCT) {
        int f = i >> 7, b = i & 127;
        INs[b*61 + f] = g_hbuf[((size_t)(t*60 + f))*BATCH + b0 + b];
    }
    __syncthreads();

    // fc1: 60 -> 50 (padded 52), packed f32x2 accumulators
    ull acc1[26];
    #pragma unroll
    for (int j = 0; j < 26; ++j) acc1[j] = pack2(B1s[2*j], B1s[2*j+1]);
    #pragma unroll 4
    for (int k = 0; k < 60; ++k) {
        float v = INs[tid*61 + k];
        ull vv = pack2(v, v);
        #pragma unroll
        for (int j = 0; j < 13; ++j) {
            ulonglong2 w = *(const ulonglong2*)(W1s + k*52 + j*4);
            acc1[2*j]   = fma2(vv, w.x, acc1[2*j]);
            acc1[2*j+1] = fma2(vv, w.y, acc1[2*j+1]);
        }
    }
    float a1[52];
    #pragma unroll
    for (int j = 0; j < 26; ++j) {
        float lo, hi; unpack2(acc1[j], lo, hi);
        a1[2*j]   = fmaxf(lo, 0.f);
        a1[2*j+1] = fmaxf(hi, 0.f);
    }

    // fc2: 50 -> 40
    ull acc2[20];
    #pragma unroll
    for (int j = 0; j < 20; ++j) acc2[j] = pack2(B2s[2*j], B2s[2*j+1]);
    #pragma unroll 5
    for (int k = 0; k < 50; ++k) {
        ull vv = pack2(a1[k], a1[k]);
        #pragma unroll
        for (int j = 0; j < 10; ++j) {
            ulonglong2 w = *(const ulonglong2*)(W2s + k*40 + j*4);
            acc2[2*j]   = fma2(vv, w.x, acc2[2*j]);
            acc2[2*j+1] = fma2(vv, w.y, acc2[2*j+1]);
        }
    }
    float a2[40];
    #pragma unroll
    for (int j = 0; j < 20; ++j) {
        float lo, hi; unpack2(acc2[j], lo, hi);
        a2[2*j]   = fmaxf(lo, 0.f);
        a2[2*j+1] = fmaxf(hi, 0.f);
    }

    // out: 40 -> 2
    float o0 = B3s[0], o1 = B3s[1];
    #pragma unroll
    for (int k = 0; k < 40; ++k) {
        o0 = fmaf(a2[k], W3s[2*k + 0], o0);
        o1 = fmaf(a2[k], W3s[2*k + 1], o1);
    }
    // out layout [B][T][2]
    float2 ov = make_float2(o0, o1);
    *(float2*)(&out[((size_t)(b0 + tid) * T_STEPS + t) * 2]) = ov;
}

// ============================================================================
extern "C" void kernel_launch(void* const* d_in, const int* in_sizes, int n_in,
                              void* d_out, int out_size)
{
    const float* x     = (const float*)d_in[0];
    const float* fw_W1 = (const float*)d_in[1];
    const float* fw_b1 = (const float*)d_in[2];
    const float* fw_W2 = (const float*)d_in[3];
    const float* fw_b2 = (const float*)d_in[4];
    const float* bw_W1 = (const float*)d_in[5];
    const float* bw_b1 = (const float*)d_in[6];
    const float* bw_W2 = (const float*)d_in[7];
    const float* bw_b2 = (const float*)d_in[8];
    const float* Wf1   = (const float*)d_in[9];
    const float* bf1   = (const float*)d_in[10];
    const float* Wf2   = (const float*)d_in[11];
    const float* bf2   = (const float*)d_in[12];
    const float* Wf3   = (const float*)d_in[13];
    const float* bf3   = (const float*)d_in[14];

    cudaFuncSetAttribute(lstm_kernel, cudaFuncAttributeMaxDynamicSharedMemorySize,
                         SM_FLOATS * (int)sizeof(float));
    cudaFuncSetAttribute(fc_kernel, cudaFuncAttributeMaxDynamicSharedMemorySize,
                         FSM_FLOATS * (int)sizeof(float));

    lstm_kernel<<<dim3(NBLK, 2), NT, SM_FLOATS * sizeof(float)>>>(
        x, fw_W1, fw_b1, fw_W2, fw_b2, bw_W1, bw_b1, bw_W2, bw_b2);

    fc_kernel<<<32 * T_STEPS, FCT, FSM_FLOATS * sizeof(float)>>>(
        Wf1, bf1, Wf2, bf2, Wf3, bf3, (float*)d_out);
}

// round 5
// speedup vs baseline: 1.3856x; 1.1390x over previous
#include <cuda_runtime.h>
#include <math.h>

#define T_STEPS 300
#define DIN 39
#define H1D 35
#define H1P 36          // padded units (unit 35 = dummy zeros)
#define H2D 30
#define G1 140
#define G1P 144         // padded gate count (36 units * 4)
#define G2 120
#define K1 74
#define K2 65
#define BT 64
#define BTP 68
#define NT 576
#define BATCH 4096
#define NBLK (BATCH/BT)

typedef unsigned long long ull;

// ---- shared memory layout (float offsets) ----
#define OFF_W1D 0                          // 74*288 = 21312 (duplicated, unit-major, padded)
#define OFF_W2D (OFF_W1D + K1*2*G1P)       // 21312, size 65*240 = 15600
#define OFF_B1  (OFF_W2D + K2*2*G2)        // 36912, 144
#define OFF_B2  (OFF_B1 + G1P)             // 37056, 120
#define OFF_X   (OFF_B2 + G2)              // 37176, 2*39*68 = 5304
#define OFF_H1  (OFF_X + 2*DIN*BTP)        // 42480, 2*36*68 = 4896
#define OFF_H2  (OFF_H1 + 2*H1P*BTP)       // 47376, 2*30*68 = 4080
#define SM_FLOATS (OFF_H2 + 2*H2D*BTP)     // 51456 floats = 205824 B

#define X_BUF  (DIN*BTP)
#define H1_BUF (H1P*BTP)
#define H2_BUF (H2D*BTP)

// scratch for LSTM hidden states: [T][60][B], fw units in [0,30), bw in [30,60)
__device__ float g_hbuf[(size_t)BATCH * T_STEPS * 60];

__device__ __forceinline__ ull fma2(ull a, ull b, ull c) {
    ull d;
    asm("fma.rn.f32x2 %0, %1, %2, %3;" : "=l"(d) : "l"(a), "l"(b), "l"(c));
    return d;
}
__device__ __forceinline__ ull pack2(float lo, float hi) {
    ull d;
    asm("mov.b64 %0, {%1, %2};" : "=l"(d) : "f"(lo), "f"(hi));
    return d;
}
__device__ __forceinline__ void unpack2(ull v, float& lo, float& hi) {
    asm("mov.b64 {%0, %1}, %2;" : "=f"(lo), "=f"(hi) : "l"(v));
}

__device__ __forceinline__ float sigf(float x) {
    return __fdividef(1.0f, 1.0f + __expf(-x));
}
__device__ __forceinline__ float tanhfast(float x) {
    return 2.0f * sigf(2.0f * x) - 1.0f;
}

// cell update on a packed pair of batch lanes; gate order i, j, f, o
__device__ __forceinline__ void cell2(ull zi, ull zj, ull zf, ull zo,
                                      ull& c, float& h0, float& h1)
{
    float i0,i1,j0,j1,f0,f1,o0,o1,c0,c1;
    unpack2(zi,i0,i1); unpack2(zj,j0,j1);
    unpack2(zf,f0,f1); unpack2(zo,o0,o1);
    unpack2(c,c0,c1);
    c0 = sigf(f0 + 1.0f) * c0 + sigf(i0) * tanhfast(j0);
    c1 = sigf(f1 + 1.0f) * c1 + sigf(i1) * tanhfast(j1);
    h0 = sigf(o0) * tanhfast(c0);
    h1 = sigf(o1) * tanhfast(c1);
    c = pack2(c0, c1);
}

// 4-gate x 2-packed-batch tile (4 batch lanes per thread).
// wd: duplicated weights (ull view, WS ull per k row); a: activation row.
template<int KN, int WS>
__device__ __forceinline__ void gemm2(ull (&acc)[4][2],
                                      const ull* __restrict__ wd,
                                      const float* __restrict__ a)
{
    #pragma unroll 5
    for (int k = 0; k < KN; ++k) {
        ulonglong2 w01 = *(const ulonglong2*)(wd);
        ulonglong2 w23 = *(const ulonglong2*)(wd + 2);
        ulonglong2 av  = *(const ulonglong2*)(a);
        wd += WS; a += BTP;
        acc[0][0] = fma2(w01.x, av.x, acc[0][0]);
        acc[0][1] = fma2(w01.x, av.y, acc[0][1]);
        acc[1][0] = fma2(w01.y, av.x, acc[1][0]);
        acc[1][1] = fma2(w01.y, av.y, acc[1][1]);
        acc[2][0] = fma2(w23.x, av.x, acc[2][0]);
        acc[2][1] = fma2(w23.x, av.y, acc[2][1]);
        acc[3][0] = fma2(w23.y, av.x, acc[3][0]);
        acc[3][1] = fma2(w23.y, av.y, acc[3][1]);
    }
}

extern __shared__ float smem[];

__global__ void __launch_bounds__(NT)
lstm_kernel(const float* __restrict__ x,
            const float* __restrict__ fw_W1, const float* __restrict__ fw_b1,
            const float* __restrict__ fw_W2, const float* __restrict__ fw_b2,
            const float* __restrict__ bw_W1, const float* __restrict__ bw_b1,
            const float* __restrict__ bw_W2, const float* __restrict__ bw_b2)
{
    const int dir = blockIdx.y;
    const int b0  = blockIdx.x * BT;
    const int tid = threadIdx.x;

    float* W1d = smem + OFF_W1D;
    float* W2d = smem + OFF_W2D;
    float* b1p = smem + OFF_B1;
    float* b2p = smem + OFF_B2;
    float* xT  = smem + OFF_X;
    float* h1T = smem + OFF_H1;
    float* h2T = smem + OFF_H2;

    const float* W1g = dir ? bw_W1 : fw_W1;
    const float* b1g = dir ? bw_b1 : fw_b1;
    const float* W2g = dir ? bw_W2 : fw_W2;
    const float* b2g = dir ? bw_b2 : fw_b2;

    // permute (unit-major gate order i,j,f,o) + duplicate weights for f32x2.
    // layer 1 padded to 36 units; unit 35 is all-zero.
    for (int i = tid; i < K1*G1P; i += NT) {
        int k = i / G1P, col = i - k * G1P;
        int u = col >> 2, g = col & 3;
        float w = (u < H1D) ? W1g[k*G1 + g*H1D + u] : 0.f;
        W1d[k*2*G1P + 2*col]     = w;
        W1d[k*2*G1P + 2*col + 1] = w;
    }
    for (int i = tid; i < K2*G2; i += NT) {
        int k = i / G2, col = i - k * G2;
        int u = col >> 2, g = col & 3;
        float w = W2g[k*G2 + g*H2D + u];
        W2d[k*2*G2 + 2*col]     = w;
        W2d[k*2*G2 + 2*col + 1] = w;
    }
    for (int i = tid; i < G1P; i += NT) {
        int u = i >> 2, g = i & 3;
        b1p[i] = (u < H1D) ? b1g[g*H1D + u] : 0.f;
    }
    for (int i = tid; i < G2; i += NT) { int u = i >> 2, g = i & 3; b2p[i] = b2g[g*H2D + u]; }
    for (int i = tid; i < H1_BUF; i += NT) { h1T[i] = 0.f; h1T[H1_BUF + i] = 0.f; }
    for (int i = tid; i < H2_BUF; i += NT) { h2T[i] = 0.f; h2T[H2_BUF + i] = 0.f; }

    // stage x for t=0 into buffer 0
    {
        const int tx0 = dir ? (T_STEPS - 1) : 0;
        for (int i = tid; i < DIN*BT; i += NT) {
            int b = i / DIN, d = i - b * DIN;
            xT[d * BTP + b] = x[((size_t)(b0 + b) * T_STEPS + tx0) * DIN + d];
        }
    }
    __syncthreads();

    const int unit = tid >> 4;          // 0..35 (35 = dummy)
    const int bcol = (tid & 15) * 4;    // 4 batch lanes per thread

    ull c1r[2] = {0,0};
    ull c2r[2] = {0,0};

    int cur = 0;

    for (int t = 0; t < T_STEPS; ++t) {
        const int nxt = cur ^ 1;
        const float* xc  = xT  + cur * X_BUF;
        const float* h1c = h1T + cur * H1_BUF;
        float*       h1n = h1T + nxt * H1_BUF;
        const float* h2c = h2T + cur * H2_BUF;
        float*       h2n = h2T + nxt * H2_BUF;

        // ====== Phase A: layer 1 — all 576 threads, exactly one task each ======
        {
            ull acc[4][2];
            #pragma unroll
            for (int g = 0; g < 4; ++g) {
                float bb = b1p[unit*4 + g];
                ull bp = pack2(bb, bb);
                acc[g][0] = bp; acc[g][1] = bp;
            }
            const ull* wd = (const ull*)W1d + unit*4;
            gemm2<DIN, G1P>(acc, wd,             xc  + bcol);
            gemm2<H1D, G1P>(acc, wd + DIN*G1P,   h1c + bcol);

            float h[4];
            cell2(acc[0][0], acc[1][0], acc[2][0], acc[3][0], c1r[0], h[0], h[1]);
            cell2(acc[0][1], acc[1][1], acc[2][1], acc[3][1], c1r[1], h[2], h[3]);
            *(float4*)(h1n + unit*BTP + bcol) = make_float4(h[0], h[1], h[2], h[3]);
        }
        __syncthreads();

        // ====== Phase B: layer 2 (threads 0..479) + x staging (480..575) ======
        if (tid < 480) {
            ull acc[4][2];
            #pragma unroll
            for (int g = 0; g < 4; ++g) {
                float bb = b2p[unit*4 + g];
                ull bp = pack2(bb, bb);
                acc[g][0] = bp; acc[g][1] = bp;
            }
            const ull* wd = (const ull*)W2d + unit*4;
            gemm2<H1D, G2>(acc, wd,            h1n + bcol);
            gemm2<H2D, G2>(acc, wd + H1D*G2,   h2c + bcol);

            float h[4];
            cell2(acc[0][0], acc[1][0], acc[2][0], acc[3][0], c2r[0], h[0], h[1]);
            cell2(acc[0][1], acc[1][1], acc[2][1], acc[3][1], c2r[1], h[2], h[3]);
            *(float4*)(h2n + unit*BTP + bcol) = make_float4(h[0], h[1], h[2], h[3]);

            const int tx = dir ? (T_STEPS - 1 - t) : t;
            // coalesced: [t][feat][batch]
            *(float4*)(&g_hbuf[((size_t)(tx*60 + dir*H2D + unit))*BATCH + b0 + bcol]) =
                make_float4(h[0], h[1], h[2], h[3]);
        } else if (t + 1 < T_STEPS) {
            // warps 15..17 stage x_{t+1} into the other buffer
            const int txn = dir ? (T_STEPS - 2 - t) : (t + 1);
            float* xn = xT + nxt * X_BUF;
            #pragma unroll 4
            for (int i = tid - 480; i < DIN*BT; i += 96) {
                int b = i / DIN, d = i - b * DIN;
                xn[d * BTP + b] = x[((size_t)(b0 + b) * T_STEPS + txn) * DIN + d];
            }
        }
        __syncthreads();
        cur = nxt;
    }
}

// =============================== FC head ===================================
#define FCT 128
#define FOFF_W1 0                       // 60*52 (padded cols 50,51 = 0)
#define FOFF_W2 (FOFF_W1 + 60*52)       // 3120, size 2000
#define FOFF_W3 (FOFF_W2 + 50*40)       // 5120, size 80
#define FOFF_B1 (FOFF_W3 + 80)          // 5200, size 52
#define FOFF_B2 (FOFF_B1 + 52)          // 5252, size 40
#define FOFF_B3 (FOFF_B2 + 40)          // 5292, size 4
#define FOFF_IN (FOFF_B3 + 4)           // 5296, size FCT*61
#define FSM_FLOATS (FOFF_IN + FCT*61)

__global__ void __launch_bounds__(FCT)
fc_kernel(const float* __restrict__ Wf1, const float* __restrict__ bf1,
          const float* __restrict__ Wf2, const float* __restrict__ bf2,
          const float* __restrict__ Wf3, const float* __restrict__ bf3,
          float* __restrict__ out)
{
    extern __shared__ float fsm[];
    float* W1s = fsm + FOFF_W1;
    float* W2s = fsm + FOFF_W2;
    float* W3s = fsm + FOFF_W3;
    float* B1s = fsm + FOFF_B1;
    float* B2s = fsm + FOFF_B2;
    float* B3s = fsm + FOFF_B3;
    float* INs = fsm + FOFF_IN;

    const int tid = threadIdx.x;

    for (int i = tid; i < 60*52; i += FCT) {
        int k = i / 52, j = i - k * 52;
        W1s[i] = (j < 50) ? Wf1[k*50 + j] : 0.f;
    }
    for (int i = tid; i < 50*40; i += FCT) W2s[i] = Wf2[i];
    for (int i = tid; i < 80;    i += FCT) W3s[i] = Wf3[i];
    for (int i = tid; i < 52;    i += FCT) B1s[i] = (i < 50) ? bf1[i] : 0.f;
    for (int i = tid; i < 40;    i += FCT) B2s[i] = bf2[i];
    for (int i = tid; i < 2;     i += FCT) B3s[i] = bf3[i];

    // block = (batch tile, timestep): hbuf reads coalesced in [t][feat][B] layout
    const int bi = blockIdx.x & 31;          // 32 tiles of 128 batch
    const int t  = blockIdx.x >> 5;          // 0..299
    const int b0 = bi * FCT;

    for (int i = tid; i < FCT*60; i += FCT) {
        int f = i >> 7, b = i & 127;
        INs[b*61 + f] = g_hbuf[((size_t)(t*60 + f))*BATCH + b0 + b];
    }
    __syncthreads();

    // fc1: 60 -> 50 (padded 52), packed f32x2 accumulators
    ull acc1[26];
    #pragma unroll
    for (int j = 0; j < 26; ++j) acc1[j] = pack2(B1s[2*j], B1s[2*j+1]);
    #pragma unroll 4
    for (int k = 0; k < 60; ++k) {
        float v = INs[tid*61 + k];
        ull vv = pack2(v, v);
        #pragma unroll
        for (int j = 0; j < 13; ++j) {
            ulonglong2 w = *(const ulonglong2*)(W1s + k*52 + j*4);
            acc1[2*j]   = fma2(vv, w.x, acc1[2*j]);
            acc1[2*j+1] = fma2(vv, w.y, acc1[2*j+1]);
        }
    }
    float a1[52];
    #pragma unroll
    for (int j = 0; j < 26; ++j) {
        float lo, hi; unpack2(acc1[j], lo, hi);
        a1[2*j]   = fmaxf(lo, 0.f);
        a1[2*j+1] = fmaxf(hi, 0.f);
    }

    // fc2: 50 -> 40
    ull acc2[20];
    #pragma unroll
    for (int j = 0; j < 20; ++j) acc2[j] = pack2(B2s[2*j], B2s[2*j+1]);
    #pragma unroll 5
    for (int k = 0; k < 50; ++k) {
        ull vv = pack2(a1[k], a1[k]);
        #pragma unroll
        for (int j = 0; j < 10; ++j) {
            ulonglong2 w = *(const ulonglong2*)(W2s + k*40 + j*4);
            acc2[2*j]   = fma2(vv, w.x, acc2[2*j]);
            acc2[2*j+1] = fma2(vv, w.y, acc2[2*j+1]);
        }
    }
    float a2[40];
    #pragma unroll
    for (int j = 0; j < 20; ++j) {
        float lo, hi; unpack2(acc2[j], lo, hi);
        a2[2*j]   = fmaxf(lo, 0.f);
        a2[2*j+1] = fmaxf(hi, 0.f);
    }

    // out: 40 -> 2
    float o0 = B3s[0], o1 = B3s[1];
    #pragma unroll
    for (int k = 0; k < 40; ++k) {
        o0 = fmaf(a2[k], W3s[2*k + 0], o0);
        o1 = fmaf(a2[k], W3s[2*k + 1], o1);
    }
    // out layout [B][T][2]
    float2 ov = make_float2(o0, o1);
    *(float2*)(&out[((size_t)(b0 + tid) * T_STEPS + t) * 2]) = ov;
}

// ============================================================================
extern "C" void kernel_launch(void* const* d_in, const int* in_sizes, int n_in,
                              void* d_out, int out_size)
{
    const float* x     = (const float*)d_in[0];
    const float* fw_W1 = (const float*)d_in[1];
    const float* fw_b1 = (const float*)d_in[2];
    const float* fw_W2 = (const float*)d_in[3];
    const float* fw_b2 = (const float*)d_in[4];
    const float* bw_W1 = (const float*)d_in[5];
    const float* bw_b1 = (const float*)d_in[6];
    const float* bw_W2 = (const float*)d_in[7];
    const float* bw_b2 = (const float*)d_in[8];
    const float* Wf1   = (const float*)d_in[9];
    const float* bf1   = (const float*)d_in[10];
    const float* Wf2   = (const float*)d_in[11];
    const float* bf2   = (const float*)d_in[12];
    const float* Wf3   = (const float*)d_in[13];
    const float* bf3   = (const float*)d_in[14];

    cudaFuncSetAttribute(lstm_kernel, cudaFuncAttributeMaxDynamicSharedMemorySize,
                         SM_FLOATS * (int)sizeof(float));
    cudaFuncSetAttribute(fc_kernel, cudaFuncAttributeMaxDynamicSharedMemorySize,
                         FSM_FLOATS * (int)sizeof(float));

    lstm_kernel<<<dim3(NBLK, 2), NT, SM_FLOATS * sizeof(float)>>>(
        x, fw_W1, fw_b1, fw_W2, fw_b2, bw_W1, bw_b1, bw_W2, bw_b2);

    fc_kernel<<<32 * T_STEPS, FCT, FSM_FLOATS * sizeof(float)>>>(
        Wf1, bf1, Wf2, bf2, Wf3, bf3, (float*)d_out);
}